// round 8
// baseline (speedup 1.0000x reference)
#include <cuda_runtime.h>
#include <cstdint>

// ---------------------------------------------------------------------------
// RSAComponentModel: trunk (Linear->BN->ReLU ->Linear->BN->ReLU) + 128 heads
// (Linear->ReLU->Linear). fp32 in/out.
// R7: design FROZEN (8 rounds, zero measurements; fragment layouts verified
// 3x against PTX ISA). Only change: cp.async .ca -> .cg (L1 bypass for
// streamed B tiles). tc path: mma.sync m16n8k8 tf32, 3xTF32 split,
// 128x128x16 tiles, double-buffered, pass-separated mma issue.
// ---------------------------------------------------------------------------

// scratch (device-global: allocation-free per harness rules)
__device__ float g_h[1024 * 2048];        // trunk0 output
__device__ float g_feats[1024 * 1024];    // trunk1 output
__device__ float g_z[67108864];           // heads1 output: [head][1024][512] (256 MB)
__device__ float g_a0[2048], g_c0[2048];  // folded BN0: y = t*a + c
__device__ float g_a1[1024], g_c1[1024];  // folded BN1

__global__ void prep_kernel(const float* __restrict__ b0, const float* __restrict__ gm0,
                            const float* __restrict__ be0, const float* __restrict__ m0,
                            const float* __restrict__ v0,
                            const float* __restrict__ b1, const float* __restrict__ gm1,
                            const float* __restrict__ be1, const float* __restrict__ m1,
                            const float* __restrict__ v1) {
    int i = blockIdx.x * blockDim.x + threadIdx.x;
    if (i < 2048) {
        float s = gm0[i] * rsqrtf(v0[i] + 1e-5f);
        g_a0[i] = s;
        g_c0[i] = (b0[i] - m0[i]) * s + be0[i];
    }
    if (i < 1024) {
        float s = gm1[i] * rsqrtf(v1[i] + 1e-5f);
        g_a1[i] = s;
        g_c1[i] = (b1[i] - m1[i]) * s + be1[i];
    }
}

// ---------------------------------------------------------------------------
// Epilogue: 0 = relu(acc*P1[col]+P2[col]) ; 1 = relu(acc+P1[col]) ; 2 = acc+P1[col]
template <int EPI>
__device__ __forceinline__ float epi_apply(float v, float s, float t) {
    if (EPI == 0) return fmaxf(fmaf(v, s, t), 0.f);
    if (EPI == 1) return fmaxf(v + s, 0.f);
    return v + s;
}

// ---------------------------------------------------------------------------
// cp.async helpers (.cg: L1 bypass — staged tiles have no L1 reuse)
__device__ __forceinline__ void cp_async16(void* smem_ptr, const void* gptr) {
    uint32_t s = (uint32_t)__cvta_generic_to_shared(smem_ptr);
    asm volatile("cp.async.cg.shared.global [%0], [%1], 16;\n" :: "r"(s), "l"(gptr));
}
__device__ __forceinline__ void cp_async_commit() {
    asm volatile("cp.async.commit_group;\n" ::: "memory");
}
__device__ __forceinline__ void cp_async_wait_all() {
    asm volatile("cp.async.wait_group 0;\n" ::: "memory");
}

// ---------------------------------------------------------------------------
// FFMA SGEMM (trunk0 only, K=200). 128x128x8 tiles, double-buffered.
#define BM 128
#define BN 128
#define BKK 8
#define TM 8
#define TN 8

template <int EPI>
__global__ __launch_bounds__(256, 2) void sgemm_kernel(
    const float* __restrict__ A, const float* __restrict__ B, float* __restrict__ C,
    const float* __restrict__ P1, const float* __restrict__ P2,
    int K, int lda, int ldb, int ldc) {
    __shared__ __align__(16) float As[2][BKK][BM];
    __shared__ __align__(16) float Bs[2][BKK][BN];

    const int cRow = blockIdx.y, cCol = blockIdx.x;
    A += (long)cRow * BM * lda;
    B += cCol * BN;
    C += (long)cRow * BM * ldc + cCol * BN;

    const int tid = threadIdx.x;
    const int irA = tid >> 1, icA = (tid & 1) * 4;
    const int irB = tid >> 5, icB = (tid & 31) * 4;
    const int tRow = (tid >> 4) * TM, tCol = (tid & 15) * TN;

    float acc[TM][TN];
#pragma unroll
    for (int i = 0; i < TM; i++)
#pragma unroll
        for (int j = 0; j < TN; j++) acc[i][j] = 0.f;

    {
        float4 a4 = *reinterpret_cast<const float4*>(A + (long)irA * lda + icA);
        As[0][icA + 0][irA] = a4.x;
        As[0][icA + 1][irA] = a4.y;
        As[0][icA + 2][irA] = a4.z;
        As[0][icA + 3][irA] = a4.w;
        cp_async16(&Bs[0][irB][icB], B + (long)irB * ldb + icB);
        cp_async_commit();
    }
    cp_async_wait_all();
    __syncthreads();

    int buf = 0;
    for (int k0 = BKK; k0 < K; k0 += BKK) {
        const int nb = buf ^ 1;
        float4 a4n = *reinterpret_cast<const float4*>(A + (long)irA * lda + k0 + icA);
        cp_async16(&Bs[nb][irB][icB], B + (long)(k0 + irB) * ldb + icB);
        cp_async_commit();

#pragma unroll
        for (int kk = 0; kk < BKK; kk++) {
            float rM[TM], rN[TN];
            *reinterpret_cast<float4*>(rM)     = *reinterpret_cast<const float4*>(&As[buf][kk][tRow]);
            *reinterpret_cast<float4*>(rM + 4) = *reinterpret_cast<const float4*>(&As[buf][kk][tRow + 4]);
            *reinterpret_cast<float4*>(rN)     = *reinterpret_cast<const float4*>(&Bs[buf][kk][tCol]);
            *reinterpret_cast<float4*>(rN + 4) = *reinterpret_cast<const float4*>(&Bs[buf][kk][tCol + 4]);
#pragma unroll
            for (int i = 0; i < TM; i++)
#pragma unroll
                for (int j = 0; j < TN; j++) acc[i][j] = fmaf(rM[i], rN[j], acc[i][j]);
        }

        As[nb][icA + 0][irA] = a4n.x;
        As[nb][icA + 1][irA] = a4n.y;
        As[nb][icA + 2][irA] = a4n.z;
        As[nb][icA + 3][irA] = a4n.w;
        cp_async_wait_all();
        __syncthreads();
        buf = nb;
    }

#pragma unroll
    for (int kk = 0; kk < BKK; kk++) {
        float rM[TM], rN[TN];
        *reinterpret_cast<float4*>(rM)     = *reinterpret_cast<const float4*>(&As[buf][kk][tRow]);
        *reinterpret_cast<float4*>(rM + 4) = *reinterpret_cast<const float4*>(&As[buf][kk][tRow + 4]);
        *reinterpret_cast<float4*>(rN)     = *reinterpret_cast<const float4*>(&Bs[buf][kk][tCol]);
        *reinterpret_cast<float4*>(rN + 4) = *reinterpret_cast<const float4*>(&Bs[buf][kk][tCol + 4]);
#pragma unroll
        for (int i = 0; i < TM; i++)
#pragma unroll
            for (int j = 0; j < TN; j++) acc[i][j] = fmaf(rM[i], rN[j], acc[i][j]);
    }

#pragma unroll
    for (int i = 0; i < TM; i++) {
        const int r = tRow + i;
#pragma unroll
        for (int j0 = 0; j0 < TN; j0 += 4) {
            float o[4];
#pragma unroll
            for (int j = 0; j < 4; j++) {
                const int gc = cCol * BN + tCol + j0 + j;
                float s = P1[gc];
                float t = (EPI == 0) ? P2[gc] : 0.f;
                o[j] = epi_apply<EPI>(acc[i][j0 + j], s, t);
            }
            *reinterpret_cast<float4*>(C + (long)r * ldc + tCol + j0) =
                *reinterpret_cast<float4*>(o);
        }
    }
}

// ---------------------------------------------------------------------------
// Tensor-core tf32 GEMM with 3xTF32 split (fp32-grade accuracy).
// CTA tile 128x128, BK=16, 8 warps each computing 64x32 via m16n8k8 mma.
// Requires M%128==0, N%128==0, K%16==0. Batched over blockIdx.z.

__device__ __forceinline__ void split_tf32(float v, uint32_t& hi, uint32_t& lo) {
    uint32_t u = __float_as_uint(v) & 0xFFFFE000u;   // truncate to tf32
    float r = v - __uint_as_float(u);                 // exact residual
    hi = u;
    lo = __float_as_uint(r) & 0xFFFFE000u;
}

__device__ __forceinline__ void mma_tf32(float* d, const uint32_t* a, const uint32_t* b) {
    asm volatile(
        "mma.sync.aligned.m16n8k8.row.col.f32.tf32.tf32.f32 "
        "{%0,%1,%2,%3}, {%4,%5,%6,%7}, {%8,%9}, {%0,%1,%2,%3};\n"
        : "+f"(d[0]), "+f"(d[1]), "+f"(d[2]), "+f"(d[3])
        : "r"(a[0]), "r"(a[1]), "r"(a[2]), "r"(a[3]), "r"(b[0]), "r"(b[1]));
}

#define TCBK 16
#define BMP 136   // padded stride; fragment LDS banks (8*l4+lg)%32 all-distinct
#define BNP 136

template <int EPI>
__device__ __forceinline__ void tc_compute_block(
    const float (*As)[BMP], const float (*Bs)[BNP],
    int wr, int wc, int l4, int lg, float acc[4][4][4]) {
#pragma unroll
    for (int ks = 0; ks < TCBK; ks += 8) {
        uint32_t bh[4][2], bl[4][2];
#pragma unroll
        for (int nt = 0; nt < 4; nt++) {
            const int n = wc * 32 + nt * 8 + lg;
            split_tf32(Bs[ks + l4][n],     bh[nt][0], bl[nt][0]);
            split_tf32(Bs[ks + l4 + 4][n], bh[nt][1], bl[nt][1]);
        }
#pragma unroll
        for (int mt = 0; mt < 4; mt++) {
            const int m = wr * 64 + mt * 16 + lg;
            uint32_t ah[4], al[4];
            split_tf32(As[ks + l4][m],         ah[0], al[0]);
            split_tf32(As[ks + l4][m + 8],     ah[1], al[1]);
            split_tf32(As[ks + l4 + 4][m],     ah[2], al[2]);
            split_tf32(As[ks + l4 + 4][m + 8], ah[3], al[3]);
            // pass-separated issue: >=3 independent mmas between writes to the
            // same accumulator (RAW chain 3*lat -> issue-limited)
#pragma unroll
            for (int nt = 0; nt < 4; nt++) mma_tf32(acc[mt][nt], ah, bh[nt]);  // hi*hi
#pragma unroll
            for (int nt = 0; nt < 4; nt++) mma_tf32(acc[mt][nt], al, bh[nt]);  // lo*hi
#pragma unroll
            for (int nt = 0; nt < 4; nt++) mma_tf32(acc[mt][nt], ah, bl[nt]);  // hi*lo
        }
    }
}

template <int EPI>
__global__ __launch_bounds__(256, 1) void tc_gemm_kernel(
    const float* __restrict__ A, const float* __restrict__ B, float* __restrict__ C,
    const float* __restrict__ P1, const float* __restrict__ P2,
    int K, int lda, int ldb, int ldc,
    long sA, long sB, long sC, long sP) {
    __shared__ __align__(16) float As[2][TCBK][BMP];  // As[k][m]
    __shared__ __align__(16) float Bs[2][TCBK][BNP];  // Bs[k][n]

    const long bz = blockIdx.z;
    A += sA * bz;
    B += sB * bz;
    C += sC * bz;
    const float* p1 = P1 + sP * bz;

    const int cRow = blockIdx.y, cCol = blockIdx.x;
    A += (long)cRow * 128 * lda;
    B += cCol * 128;
    C += (long)cRow * 128 * ldc + cCol * 128;

    const int tid = threadIdx.x;
    const int lane = tid & 31, w = tid >> 5;
    const int wr = w >> 2, wc = w & 3;       // warp grid 2 (m) x 4 (n)
    const int l4 = lane & 3, lg = lane >> 2; // fragment coords

    // loaders
    const int rowA = tid >> 2;         // 0..63 (and +64)
    const int kA = (tid & 3) * 4;      // 0,4,8,12
    const int irB = tid >> 5;          // 0..7 (and +8)
    const int icB = (tid & 31) * 4;

    float acc[4][4][4];
#pragma unroll
    for (int mt = 0; mt < 4; mt++)
#pragma unroll
        for (int nt = 0; nt < 4; nt++)
#pragma unroll
            for (int r = 0; r < 4; r++) acc[mt][nt][r] = 0.f;

    // ---- prologue: k-block 0 -> buffer 0 ----
    {
        float4 a40 = *reinterpret_cast<const float4*>(A + (long)rowA * lda + kA);
        float4 a41 = *reinterpret_cast<const float4*>(A + (long)(rowA + 64) * lda + kA);
        cp_async16(&Bs[0][irB][icB],     B + (long)irB * ldb + icB);
        cp_async16(&Bs[0][irB + 8][icB], B + (long)(irB + 8) * ldb + icB);
        cp_async_commit();
        As[0][kA + 0][rowA] = a40.x;
        As[0][kA + 1][rowA] = a40.y;
        As[0][kA + 2][rowA] = a40.z;
        As[0][kA + 3][rowA] = a40.w;
        As[0][kA + 0][rowA + 64] = a41.x;
        As[0][kA + 1][rowA + 64] = a41.y;
        As[0][kA + 2][rowA + 64] = a41.z;
        As[0][kA + 3][rowA + 64] = a41.w;
    }
    cp_async_wait_all();
    __syncthreads();

    int buf = 0;
    // steady state: front-batched A LDGs, async B prefetch, compute, store
    for (int k0 = TCBK; k0 < K; k0 += TCBK) {
        const int nb = buf ^ 1;
        float4 a40 = *reinterpret_cast<const float4*>(A + (long)rowA * lda + k0 + kA);
        float4 a41 = *reinterpret_cast<const float4*>(A + (long)(rowA + 64) * lda + k0 + kA);
        cp_async16(&Bs[nb][irB][icB],     B + (long)(k0 + irB) * ldb + icB);
        cp_async16(&Bs[nb][irB + 8][icB], B + (long)(k0 + irB + 8) * ldb + icB);
        cp_async_commit();

        tc_compute_block<EPI>(As[buf], Bs[buf], wr, wc, l4, lg, acc);

        As[nb][kA + 0][rowA] = a40.x;
        As[nb][kA + 1][rowA] = a40.y;
        As[nb][kA + 2][rowA] = a40.z;
        As[nb][kA + 3][rowA] = a40.w;
        As[nb][kA + 0][rowA + 64] = a41.x;
        As[nb][kA + 1][rowA + 64] = a41.y;
        As[nb][kA + 2][rowA + 64] = a41.z;
        As[nb][kA + 3][rowA + 64] = a41.w;
        cp_async_wait_all();
        __syncthreads();
        buf = nb;
    }
    // last block
    tc_compute_block<EPI>(As[buf], Bs[buf], wr, wc, l4, lg, acc);

    // ---- epilogue ----
#pragma unroll
    for (int mt = 0; mt < 4; mt++) {
        const int r0 = wr * 64 + mt * 16 + lg;
#pragma unroll
        for (int nt = 0; nt < 4; nt++) {
            const int cl = wc * 32 + nt * 8 + l4 * 2;
            const int gc = cCol * 128 + cl;
            float s0 = p1[gc], s1 = p1[gc + 1];
            float t0 = (EPI == 0) ? P2[gc] : 0.f;
            float t1 = (EPI == 0) ? P2[gc + 1] : 0.f;
            float2 o01, o23;
            o01.x = epi_apply<EPI>(acc[mt][nt][0], s0, t0);
            o01.y = epi_apply<EPI>(acc[mt][nt][1], s1, t1);
            o23.x = epi_apply<EPI>(acc[mt][nt][2], s0, t0);
            o23.y = epi_apply<EPI>(acc[mt][nt][3], s1, t1);
            *reinterpret_cast<float2*>(C + (long)r0 * ldc + cl) = o01;
            *reinterpret_cast<float2*>(C + (long)(r0 + 8) * ldc + cl) = o23;
        }
    }
}

// ---------------------------------------------------------------------------
extern "C" void kernel_launch(void* const* d_in, const int* in_sizes, int n_in,
                              void* d_out, int out_size) {
    const float* x   = (const float*)d_in[0];
    const float* W0  = (const float*)d_in[1];
    const float* b0  = (const float*)d_in[2];
    const float* gm0 = (const float*)d_in[3];
    const float* be0 = (const float*)d_in[4];
    const float* m0  = (const float*)d_in[5];
    const float* v0  = (const float*)d_in[6];
    const float* W1  = (const float*)d_in[7];
    const float* b1  = (const float*)d_in[8];
    const float* gm1 = (const float*)d_in[9];
    const float* be1 = (const float*)d_in[10];
    const float* m1  = (const float*)d_in[11];
    const float* v1  = (const float*)d_in[12];
    const float* HW1 = (const float*)d_in[13];
    const float* Hb1 = (const float*)d_in[14];
    const float* HW2 = (const float*)d_in[15];
    const float* Hb2 = (const float*)d_in[16];
    float* out = (float*)d_out;

    void *ph, *pf, *pz, *pa0, *pc0, *pa1, *pc1;
    cudaGetSymbolAddress(&ph, g_h);
    cudaGetSymbolAddress(&pf, g_feats);
    cudaGetSymbolAddress(&pz, g_z);
    cudaGetSymbolAddress(&pa0, g_a0);
    cudaGetSymbolAddress(&pc0, g_c0);
    cudaGetSymbolAddress(&pa1, g_a1);
    cudaGetSymbolAddress(&pc1, g_c1);

    prep_kernel<<<8, 256>>>(b0, gm0, be0, m0, v0, b1, gm1, be1, m1, v1);

    // trunk0: g_h[1024,2048] = relu(bn(x @ W0)), K=200 (FFMA path: K%16 != 0)
    sgemm_kernel<0><<<dim3(16, 8, 1), 256>>>(
        x, W0, (float*)ph, (const float*)pa0, (const float*)pc0,
        200, 200, 2048, 2048);

    // trunk1: g_feats[1024,1024] = relu(bn(g_h @ W1)), K=2048 (tensor cores)
    tc_gemm_kernel<0><<<dim3(8, 8, 1), 256>>>(
        (const float*)ph, W1, (float*)pf, (const float*)pa1, (const float*)pc1,
        2048, 2048, 1024, 1024, 0, 0, 0, 0);

    // heads1: g_z[n][1024,512] = relu(g_feats @ HW1[n] + Hb1[n]), K=1024
    tc_gemm_kernel<1><<<dim3(4, 8, 128), 256>>>(
        (const float*)pf, HW1, (float*)pz, Hb1, nullptr,
        1024, 1024, 512, 512,
        0L, 1024L * 512, 1024L * 512, 512L);

    // heads2: out[:, n, :] = g_z[n] @ HW2[n] + Hb2[n], K=512
    tc_gemm_kernel<2><<<dim3(2, 8, 128), 256>>>(
        (const float*)pz, HW2, out, Hb2, nullptr,
        512, 512, 256, 128 * 256,
        1024L * 512, 512L * 256, 256L, 256L);
}

// round 9
// speedup vs baseline: 1.2594x; 1.2594x over previous
#include <cuda_runtime.h>
#include <cuda_fp16.h>
#include <cstdint>

// ---------------------------------------------------------------------------
// RSAComponentModel: trunk (Linear->BN->ReLU ->Linear->BN->ReLU) + 128 heads
// (Linear->ReLU->Linear). fp32 in/out.
// R8: first measurement (R7: 2541us, tensor=72.8% on HMMA tf32 path).
// Change: 3xTF32 m16n8k8 -> split-fp16 3-pass m16n8k16 (same ~2^-21 accuracy,
// HALF the HMMA instructions). SMEM pad 136->132 for conflict-free even-k
// scalar fragment LDS. Everything else held.
// ---------------------------------------------------------------------------

// scratch (device-global: allocation-free per harness rules)
__device__ float g_h[1024 * 2048];        // trunk0 output
__device__ float g_feats[1024 * 1024];    // trunk1 output
__device__ float g_z[67108864];           // heads1 output: [head][1024][512] (256 MB)
__device__ float g_a0[2048], g_c0[2048];  // folded BN0: y = t*a + c
__device__ float g_a1[1024], g_c1[1024];  // folded BN1

__global__ void prep_kernel(const float* __restrict__ b0, const float* __restrict__ gm0,
                            const float* __restrict__ be0, const float* __restrict__ m0,
                            const float* __restrict__ v0,
                            const float* __restrict__ b1, const float* __restrict__ gm1,
                            const float* __restrict__ be1, const float* __restrict__ m1,
                            const float* __restrict__ v1) {
    int i = blockIdx.x * blockDim.x + threadIdx.x;
    if (i < 2048) {
        float s = gm0[i] * rsqrtf(v0[i] + 1e-5f);
        g_a0[i] = s;
        g_c0[i] = (b0[i] - m0[i]) * s + be0[i];
    }
    if (i < 1024) {
        float s = gm1[i] * rsqrtf(v1[i] + 1e-5f);
        g_a1[i] = s;
        g_c1[i] = (b1[i] - m1[i]) * s + be1[i];
    }
}

// ---------------------------------------------------------------------------
// Epilogue: 0 = relu(acc*P1[col]+P2[col]) ; 1 = relu(acc+P1[col]) ; 2 = acc+P1[col]
template <int EPI>
__device__ __forceinline__ float epi_apply(float v, float s, float t) {
    if (EPI == 0) return fmaxf(fmaf(v, s, t), 0.f);
    if (EPI == 1) return fmaxf(v + s, 0.f);
    return v + s;
}

// ---------------------------------------------------------------------------
// cp.async helpers (.cg: L1 bypass — staged tiles have no L1 reuse)
__device__ __forceinline__ void cp_async16(void* smem_ptr, const void* gptr) {
    uint32_t s = (uint32_t)__cvta_generic_to_shared(smem_ptr);
    asm volatile("cp.async.cg.shared.global [%0], [%1], 16;\n" :: "r"(s), "l"(gptr));
}
__device__ __forceinline__ void cp_async_commit() {
    asm volatile("cp.async.commit_group;\n" ::: "memory");
}
__device__ __forceinline__ void cp_async_wait_all() {
    asm volatile("cp.async.wait_group 0;\n" ::: "memory");
}

// ---------------------------------------------------------------------------
// FFMA SGEMM (trunk0 only, K=200). 128x128x8 tiles, double-buffered.
#define BM 128
#define BN 128
#define BKK 8
#define TM 8
#define TN 8

template <int EPI>
__global__ __launch_bounds__(256, 2) void sgemm_kernel(
    const float* __restrict__ A, const float* __restrict__ B, float* __restrict__ C,
    const float* __restrict__ P1, const float* __restrict__ P2,
    int K, int lda, int ldb, int ldc) {
    __shared__ __align__(16) float As[2][BKK][BM];
    __shared__ __align__(16) float Bs[2][BKK][BN];

    const int cRow = blockIdx.y, cCol = blockIdx.x;
    A += (long)cRow * BM * lda;
    B += cCol * BN;
    C += (long)cRow * BM * ldc + cCol * BN;

    const int tid = threadIdx.x;
    const int irA = tid >> 1, icA = (tid & 1) * 4;
    const int irB = tid >> 5, icB = (tid & 31) * 4;
    const int tRow = (tid >> 4) * TM, tCol = (tid & 15) * TN;

    float acc[TM][TN];
#pragma unroll
    for (int i = 0; i < TM; i++)
#pragma unroll
        for (int j = 0; j < TN; j++) acc[i][j] = 0.f;

    {
        float4 a4 = *reinterpret_cast<const float4*>(A + (long)irA * lda + icA);
        As[0][icA + 0][irA] = a4.x;
        As[0][icA + 1][irA] = a4.y;
        As[0][icA + 2][irA] = a4.z;
        As[0][icA + 3][irA] = a4.w;
        cp_async16(&Bs[0][irB][icB], B + (long)irB * ldb + icB);
        cp_async_commit();
    }
    cp_async_wait_all();
    __syncthreads();

    int buf = 0;
    for (int k0 = BKK; k0 < K; k0 += BKK) {
        const int nb = buf ^ 1;
        float4 a4n = *reinterpret_cast<const float4*>(A + (long)irA * lda + k0 + icA);
        cp_async16(&Bs[nb][irB][icB], B + (long)(k0 + irB) * ldb + icB);
        cp_async_commit();

#pragma unroll
        for (int kk = 0; kk < BKK; kk++) {
            float rM[TM], rN[TN];
            *reinterpret_cast<float4*>(rM)     = *reinterpret_cast<const float4*>(&As[buf][kk][tRow]);
            *reinterpret_cast<float4*>(rM + 4) = *reinterpret_cast<const float4*>(&As[buf][kk][tRow + 4]);
            *reinterpret_cast<float4*>(rN)     = *reinterpret_cast<const float4*>(&Bs[buf][kk][tCol]);
            *reinterpret_cast<float4*>(rN + 4) = *reinterpret_cast<const float4*>(&Bs[buf][kk][tCol + 4]);
#pragma unroll
            for (int i = 0; i < TM; i++)
#pragma unroll
                for (int j = 0; j < TN; j++) acc[i][j] = fmaf(rM[i], rN[j], acc[i][j]);
        }

        As[nb][icA + 0][irA] = a4n.x;
        As[nb][icA + 1][irA] = a4n.y;
        As[nb][icA + 2][irA] = a4n.z;
        As[nb][icA + 3][irA] = a4n.w;
        cp_async_wait_all();
        __syncthreads();
        buf = nb;
    }

#pragma unroll
    for (int kk = 0; kk < BKK; kk++) {
        float rM[TM], rN[TN];
        *reinterpret_cast<float4*>(rM)     = *reinterpret_cast<const float4*>(&As[buf][kk][tRow]);
        *reinterpret_cast<float4*>(rM + 4) = *reinterpret_cast<const float4*>(&As[buf][kk][tRow + 4]);
        *reinterpret_cast<float4*>(rN)     = *reinterpret_cast<const float4*>(&Bs[buf][kk][tCol]);
        *reinterpret_cast<float4*>(rN + 4) = *reinterpret_cast<const float4*>(&Bs[buf][kk][tCol + 4]);
#pragma unroll
        for (int i = 0; i < TM; i++)
#pragma unroll
            for (int j = 0; j < TN; j++) acc[i][j] = fmaf(rM[i], rN[j], acc[i][j]);
    }

#pragma unroll
    for (int i = 0; i < TM; i++) {
        const int r = tRow + i;
#pragma unroll
        for (int j0 = 0; j0 < TN; j0 += 4) {
            float o[4];
#pragma unroll
            for (int j = 0; j < 4; j++) {
                const int gc = cCol * BN + tCol + j0 + j;
                float s = P1[gc];
                float t = (EPI == 0) ? P2[gc] : 0.f;
                o[j] = epi_apply<EPI>(acc[i][j0 + j], s, t);
            }
            *reinterpret_cast<float4*>(C + (long)r * ldc + tCol + j0) =
                *reinterpret_cast<float4*>(o);
        }
    }
}

// ---------------------------------------------------------------------------
// Tensor-core split-fp16 GEMM (3-pass Markidis: hh + lh + hl, err ~2^-21).
// CTA tile 128x128, BK=16 (one m16n8k16 K-step), 8 warps each 64x32.
// Requires M%128==0, N%128==0, K%16==0. Batched over blockIdx.z.

__device__ __forceinline__ uint32_t h2u(__half2 h) {
    return *reinterpret_cast<uint32_t*>(&h);
}

// split v0,v1 (consecutive k) into packed hi/lo half2 (low 16 bits = v0)
__device__ __forceinline__ void split_pack(float v0, float v1, uint32_t& hi, uint32_t& lo) {
    __half h0 = __float2half_rn(v0);
    __half h1 = __float2half_rn(v1);
    float r0 = v0 - __half2float(h0);
    float r1 = v1 - __half2float(h1);
    hi = h2u(__halves2half2(h0, h1));
    lo = h2u(__floats2half2_rn(r0, r1));
}

__device__ __forceinline__ void mma_f16(float* d, const uint32_t* a, const uint32_t* b) {
    asm volatile(
        "mma.sync.aligned.m16n8k16.row.col.f32.f16.f16.f32 "
        "{%0,%1,%2,%3}, {%4,%5,%6,%7}, {%8,%9}, {%0,%1,%2,%3};\n"
        : "+f"(d[0]), "+f"(d[1]), "+f"(d[2]), "+f"(d[3])
        : "r"(a[0]), "r"(a[1]), "r"(a[2]), "r"(a[3]), "r"(b[0]), "r"(b[1]));
}

#define TCBK 16
#define BMP 132   // pad: 132%32==4 -> even-k fragment LDS banks 8*l4+lg+4c, conflict-free
#define BNP 132

template <int EPI>
__device__ __forceinline__ void tc_compute_block(
    const float (*As)[BMP], const float (*Bs)[BNP],
    int wr, int wc, int l4, int lg, float acc[4][4][4]) {
    const int k0 = 2 * l4, k1 = k0 + 1, k2 = k0 + 8, k3 = k0 + 9;

    uint32_t bh[4][2], bl[4][2];
#pragma unroll
    for (int nt = 0; nt < 4; nt++) {
        const int n = wc * 32 + nt * 8 + lg;
        split_pack(Bs[k0][n], Bs[k1][n], bh[nt][0], bl[nt][0]);
        split_pack(Bs[k2][n], Bs[k3][n], bh[nt][1], bl[nt][1]);
    }
#pragma unroll
    for (int mt = 0; mt < 4; mt++) {
        const int m = wr * 64 + mt * 16 + lg;
        uint32_t ah[4], al[4];
        split_pack(As[k0][m],     As[k1][m],     ah[0], al[0]);  // a0: row g,   k[0,8)
        split_pack(As[k0][m + 8], As[k1][m + 8], ah[1], al[1]);  // a1: row g+8, k[0,8)
        split_pack(As[k2][m],     As[k3][m],     ah[2], al[2]);  // a2: row g,   k[8,16)
        split_pack(As[k2][m + 8], As[k3][m + 8], ah[3], al[3]);  // a3: row g+8, k[8,16)
        // pass-separated issue: >=3 independent mmas between same-acc writes
#pragma unroll
        for (int nt = 0; nt < 4; nt++) mma_f16(acc[mt][nt], ah, bh[nt]);  // hi*hi
#pragma unroll
        for (int nt = 0; nt < 4; nt++) mma_f16(acc[mt][nt], al, bh[nt]);  // lo*hi
#pragma unroll
        for (int nt = 0; nt < 4; nt++) mma_f16(acc[mt][nt], ah, bl[nt]);  // hi*lo
    }
}

template <int EPI>
__global__ __launch_bounds__(256, 1) void tc_gemm_kernel(
    const float* __restrict__ A, const float* __restrict__ B, float* __restrict__ C,
    const float* __restrict__ P1, const float* __restrict__ P2,
    int K, int lda, int ldb, int ldc,
    long sA, long sB, long sC, long sP) {
    __shared__ __align__(16) float As[2][TCBK][BMP];  // As[k][m]
    __shared__ __align__(16) float Bs[2][TCBK][BNP];  // Bs[k][n]

    const long bz = blockIdx.z;
    A += sA * bz;
    B += sB * bz;
    C += sC * bz;
    const float* p1 = P1 + sP * bz;

    const int cRow = blockIdx.y, cCol = blockIdx.x;
    A += (long)cRow * 128 * lda;
    B += cCol * 128;
    C += (long)cRow * 128 * ldc + cCol * 128;

    const int tid = threadIdx.x;
    const int lane = tid & 31, w = tid >> 5;
    const int wr = w >> 2, wc = w & 3;       // warp grid 2 (m) x 4 (n)
    const int l4 = lane & 3, lg = lane >> 2; // fragment coords (t, g)

    // loaders
    const int rowA = tid >> 2;         // 0..63 (and +64)
    const int kA = (tid & 3) * 4;      // 0,4,8,12
    const int irB = tid >> 5;          // 0..7 (and +8)
    const int icB = (tid & 31) * 4;

    float acc[4][4][4];
#pragma unroll
    for (int mt = 0; mt < 4; mt++)
#pragma unroll
        for (int nt = 0; nt < 4; nt++)
#pragma unroll
            for (int r = 0; r < 4; r++) acc[mt][nt][r] = 0.f;

    // ---- prologue: k-block 0 -> buffer 0 ----
    {
        float4 a40 = *reinterpret_cast<const float4*>(A + (long)rowA * lda + kA);
        float4 a41 = *reinterpret_cast<const float4*>(A + (long)(rowA + 64) * lda + kA);
        cp_async16(&Bs[0][irB][icB],     B + (long)irB * ldb + icB);
        cp_async16(&Bs[0][irB + 8][icB], B + (long)(irB + 8) * ldb + icB);
        cp_async_commit();
        As[0][kA + 0][rowA] = a40.x;
        As[0][kA + 1][rowA] = a40.y;
        As[0][kA + 2][rowA] = a40.z;
        As[0][kA + 3][rowA] = a40.w;
        As[0][kA + 0][rowA + 64] = a41.x;
        As[0][kA + 1][rowA + 64] = a41.y;
        As[0][kA + 2][rowA + 64] = a41.z;
        As[0][kA + 3][rowA + 64] = a41.w;
    }
    cp_async_wait_all();
    __syncthreads();

    int buf = 0;
    // steady state: front-batched A LDGs, async B prefetch, compute, store
    for (int k0 = TCBK; k0 < K; k0 += TCBK) {
        const int nb = buf ^ 1;
        float4 a40 = *reinterpret_cast<const float4*>(A + (long)rowA * lda + k0 + kA);
        float4 a41 = *reinterpret_cast<const float4*>(A + (long)(rowA + 64) * lda + k0 + kA);
        cp_async16(&Bs[nb][irB][icB],     B + (long)(k0 + irB) * ldb + icB);
        cp_async16(&Bs[nb][irB + 8][icB], B + (long)(k0 + irB + 8) * ldb + icB);
        cp_async_commit();

        tc_compute_block<EPI>(As[buf], Bs[buf], wr, wc, l4, lg, acc);

        As[nb][kA + 0][rowA] = a40.x;
        As[nb][kA + 1][rowA] = a40.y;
        As[nb][kA + 2][rowA] = a40.z;
        As[nb][kA + 3][rowA] = a40.w;
        As[nb][kA + 0][rowA + 64] = a41.x;
        As[nb][kA + 1][rowA + 64] = a41.y;
        As[nb][kA + 2][rowA + 64] = a41.z;
        As[nb][kA + 3][rowA + 64] = a41.w;
        cp_async_wait_all();
        __syncthreads();
        buf = nb;
    }
    // last block
    tc_compute_block<EPI>(As[buf], Bs[buf], wr, wc, l4, lg, acc);

    // ---- epilogue (m16n8k16 C fragment == m16n8k8 C fragment) ----
#pragma unroll
    for (int mt = 0; mt < 4; mt++) {
        const int r0 = wr * 64 + mt * 16 + lg;
#pragma unroll
        for (int nt = 0; nt < 4; nt++) {
            const int cl = wc * 32 + nt * 8 + l4 * 2;
            const int gc = cCol * 128 + cl;
            float s0 = p1[gc], s1 = p1[gc + 1];
            float t0 = (EPI == 0) ? P2[gc] : 0.f;
            float t1 = (EPI == 0) ? P2[gc + 1] : 0.f;
            float2 o01, o23;
            o01.x = epi_apply<EPI>(acc[mt][nt][0], s0, t0);
            o01.y = epi_apply<EPI>(acc[mt][nt][1], s1, t1);
            o23.x = epi_apply<EPI>(acc[mt][nt][2], s0, t0);
            o23.y = epi_apply<EPI>(acc[mt][nt][3], s1, t1);
            *reinterpret_cast<float2*>(C + (long)r0 * ldc + cl) = o01;
            *reinterpret_cast<float2*>(C + (long)(r0 + 8) * ldc + cl) = o23;
        }
    }
}

// ---------------------------------------------------------------------------
extern "C" void kernel_launch(void* const* d_in, const int* in_sizes, int n_in,
                              void* d_out, int out_size) {
    const float* x   = (const float*)d_in[0];
    const float* W0  = (const float*)d_in[1];
    const float* b0  = (const float*)d_in[2];
    const float* gm0 = (const float*)d_in[3];
    const float* be0 = (const float*)d_in[4];
    const float* m0  = (const float*)d_in[5];
    const float* v0  = (const float*)d_in[6];
    const float* W1  = (const float*)d_in[7];
    const float* b1  = (const float*)d_in[8];
    const float* gm1 = (const float*)d_in[9];
    const float* be1 = (const float*)d_in[10];
    const float* m1  = (const float*)d_in[11];
    const float* v1  = (const float*)d_in[12];
    const float* HW1 = (const float*)d_in[13];
    const float* Hb1 = (const float*)d_in[14];
    const float* HW2 = (const float*)d_in[15];
    const float* Hb2 = (const float*)d_in[16];
    float* out = (float*)d_out;

    void *ph, *pf, *pz, *pa0, *pc0, *pa1, *pc1;
    cudaGetSymbolAddress(&ph, g_h);
    cudaGetSymbolAddress(&pf, g_feats);
    cudaGetSymbolAddress(&pz, g_z);
    cudaGetSymbolAddress(&pa0, g_a0);
    cudaGetSymbolAddress(&pc0, g_c0);
    cudaGetSymbolAddress(&pa1, g_a1);
    cudaGetSymbolAddress(&pc1, g_c1);

    prep_kernel<<<8, 256>>>(b0, gm0, be0, m0, v0, b1, gm1, be1, m1, v1);

    // trunk0: g_h[1024,2048] = relu(bn(x @ W0)), K=200 (FFMA path: K%16 != 0)
    sgemm_kernel<0><<<dim3(16, 8, 1), 256>>>(
        x, W0, (float*)ph, (const float*)pa0, (const float*)pc0,
        200, 200, 2048, 2048);

    // trunk1: g_feats[1024,1024] = relu(bn(g_h @ W1)), K=2048 (tensor cores)
    tc_gemm_kernel<0><<<dim3(8, 8, 1), 256>>>(
        (const float*)ph, W1, (float*)pf, (const float*)pa1, (const float*)pc1,
        2048, 2048, 1024, 1024, 0, 0, 0, 0);

    // heads1: g_z[n][1024,512] = relu(g_feats @ HW1[n] + Hb1[n]), K=1024
    tc_gemm_kernel<1><<<dim3(4, 8, 128), 256>>>(
        (const float*)pf, HW1, (float*)pz, Hb1, nullptr,
        1024, 1024, 512, 512,
        0L, 1024L * 512, 1024L * 512, 512L);

    // heads2: out[:, n, :] = g_z[n] @ HW2[n] + Hb2[n], K=512
    tc_gemm_kernel<2><<<dim3(2, 8, 128), 256>>>(
        (const float*)pz, HW2, out, Hb2, nullptr,
        512, 512, 256, 128 * 256,
        1024L * 512, 512L * 256, 256L, 256L);
}